// round 1
// baseline (speedup 1.0000x reference)
#include <cuda_runtime.h>
#include <math.h>

#define BATCH 4
#define SPAST 1024
#define SFUT 512
#define NTOK 1536
#define DM 256
#define NH 8
#define DH 32
#define DFF 2048
#define NLAYERS 8
#define NROWS (BATCH*NTOK)        // 6144
#define CHUNK 128
#define NCHUNK (NTOK/CHUNK)       // 12
#define NBH (BATCH*NH)            // 32

// ---------------- scratch (no allocation allowed) ----------------
__device__ float g_x  [NROWS*DM];
__device__ float g_tmp[NROWS*DM];
__device__ float g_qb [NROWS*DM];
__device__ float g_kb [NROWS*DM];
__device__ float g_vb [NROWS*DM];
__device__ float g_ab [NROWS*DM];
__device__ float g_hb [NROWS*DFF];
__device__ float g_Sloc[NBH*NCHUNK*DH*DH];
__device__ float g_Spre[NBH*NCHUNK*DH*DH];
__device__ float g_kloc[NBH*NCHUNK*DH];
__device__ float g_kpre[NBH*NCHUNK*DH];

// ---------------- packed fp32x2 helpers (sm_103a) ----------------
__device__ __forceinline__ unsigned long long pack2(float v){
    unsigned long long r;
    unsigned int u = __float_as_uint(v);
    asm("mov.b64 %0, {%1, %1};" : "=l"(r) : "r"(u));
    return r;
}
__device__ __forceinline__ void fma2(unsigned long long &d, unsigned long long a, unsigned long long b){
    asm("fma.rn.f32x2 %0, %1, %2, %0;" : "+l"(d) : "l"(a), "l"(b));
}
__device__ __forceinline__ float2 unp2(unsigned long long v){
    unsigned int lo, hi;
    asm("mov.b64 {%0, %1}, %2;" : "=r"(lo), "=r"(hi) : "l"(v));
    return make_float2(__uint_as_float(lo), __uint_as_float(hi));
}

// ---------------- embedding: x = concat(x_in, y_in) @ enc_W + enc_b ----------------
__global__ void embed_kernel(const float* __restrict__ px, const float* __restrict__ py,
                             const float* __restrict__ fx,
                             const float* __restrict__ W, const float* __restrict__ b,
                             float* __restrict__ x)
{
    __shared__ float s[24];
    int r = blockIdx.x;
    int bb = r / NTOK, n = r % NTOK;
    int t = threadIdx.x;
    if (t < 24) {
        float v;
        if (t < 16) {
            v = (n < SPAST) ? px[(bb*SPAST+n)*16+t] : fx[(bb*SFUT+(n-SPAST))*16+t];
        } else {
            int yn = (n < SPAST) ? n : (SPAST-1);
            v = py[(bb*SPAST+yn)*8 + (t-16)];
        }
        s[t] = v;
    }
    __syncthreads();
    float acc = b[t];
    #pragma unroll
    for (int kk=0; kk<24; kk++) acc = fmaf(s[kk], W[kk*DM+t], acc);
    x[(size_t)r*DM + t] = acc;
}

// ---------------- GEMM: C = epi(A[M,K] @ B[K,N] + bias [+res]) ----------------
// EPI: 0 = bias, 1 = elu+1(bias), 2 = relu(bias), 3 = bias + residual
#define GBM 128
#define GBN 64
#define GBK 16

template<int EPI>
__global__ void __launch_bounds__(256) sgemm_kernel(
    int K, int N,
    const float* __restrict__ A, const float* __restrict__ B,
    const float* __restrict__ bias, const float* __restrict__ res,
    float* __restrict__ C)
{
    __shared__ float As[GBK][GBM+2];   // A transposed, +2 pad (keeps 8B align, kills bank conflicts)
    __shared__ float Bs[GBK][GBN];
    const int t  = threadIdx.x;
    const int tx = t & 15;             // N direction (16 x 4 = 64)
    const int ty = t >> 4;             // M direction (16 x 8 = 128)
    const int bm = blockIdx.y * GBM;
    const int bn = blockIdx.x * GBN;

    unsigned long long acc[4][4];      // [m-pair][n] ; pair = rows (ty*8+2p, ty*8+2p+1)
    #pragma unroll
    for (int p=0;p<4;p++)
        #pragma unroll
        for (int j=0;j<4;j++) acc[p][j] = 0ull;

    const int arow0 = t >> 2;          // 0..63
    const int akq   = (t & 3) * 4;     // k offset 0,4,8,12
    const int brow  = t >> 4;          // 0..15
    const int bcol  = (t & 15) * 4;

    for (int k0=0; k0<K; k0+=GBK){
        #pragma unroll
        for (int l=0;l<2;l++){
            int row = arow0 + l*64;
            float4 av = *(const float4*)(A + (size_t)(bm+row)*K + k0 + akq);
            As[akq+0][row]=av.x; As[akq+1][row]=av.y; As[akq+2][row]=av.z; As[akq+3][row]=av.w;
        }
        *(float4*)&Bs[brow][bcol] = *(const float4*)(B + (size_t)(k0+brow)*N + bn + bcol);
        __syncthreads();
        #pragma unroll
        for (int kk=0;kk<GBK;kk++){
            const unsigned long long* arow = (const unsigned long long*)&As[kk][0];
            unsigned long long a2[4];
            #pragma unroll
            for (int p=0;p<4;p++) a2[p] = arow[ty*4+p];
            unsigned long long bb2[4];
            #pragma unroll
            for (int j=0;j<4;j++) bb2[j] = pack2(Bs[kk][tx*4+j]);
            #pragma unroll
            for (int p=0;p<4;p++)
                #pragma unroll
                for (int j=0;j<4;j++) fma2(acc[p][j], a2[p], bb2[j]);
        }
        __syncthreads();
    }

    #pragma unroll
    for (int p=0;p<4;p++){
        float2 u[4];
        #pragma unroll
        for (int j=0;j<4;j++) u[j] = unp2(acc[p][j]);
        #pragma unroll
        for (int half=0; half<2; half++){
            int row = bm + ty*8 + 2*p + half;
            float cv[4];
            #pragma unroll
            for (int j=0;j<4;j++){
                float vv = (half==0)? u[j].x : u[j].y;
                int col = bn + tx*4 + j;
                vv += bias[col];
                if (EPI==1) vv = (vv>=0.f)? vv+1.f : expf(vv);   // elu(x)+1
                if (EPI==2) vv = fmaxf(vv, 0.f);
                if (EPI==3) vv += res[(size_t)row*N + col];
                cv[j]=vv;
            }
            float4 o; o.x=cv[0]; o.y=cv[1]; o.z=cv[2]; o.w=cv[3];
            *(float4*)(C + (size_t)row*N + bn + tx*4) = o;
        }
    }
}

// ---------------- per-chunk K^T V state + K column sums ----------------
__global__ void __launch_bounds__(1024) chunk_kv_kernel(const float* __restrict__ k,
                                                        const float* __restrict__ v)
{
    int c = blockIdx.x, bh = blockIdx.y;
    int b = bh >> 3, h = bh & 7;
    __shared__ float ks[CHUNK][DH];
    __shared__ float vs[CHUNK][DH];
    int t = threadIdx.x;
    int base = b*NTOK + c*CHUNK;
    for (int idx=t; idx<CHUNK*DH; idx+=1024){
        int row = idx >> 5, col = idx & 31;
        size_t g = (size_t)(base+row)*DM + h*DH + col;
        ks[row][col] = k[g];
        vs[row][col] = v[g];
    }
    __syncthreads();
    int d = t >> 5, m = t & 31;
    float s = 0.f;
    #pragma unroll 8
    for (int j=0;j<CHUNK;j++) s = fmaf(ks[j][d], vs[j][m], s);
    g_Sloc[((size_t)bh*NCHUNK + c)*DH*DH + d*DH + m] = s;
    if (t < DH){
        float kssum = 0.f;
        #pragma unroll 8
        for (int j=0;j<CHUNK;j++) kssum += ks[j][t];
        g_kloc[((size_t)bh*NCHUNK + c)*DH + t] = kssum;
    }
}

// ---------------- exclusive prefix over chunks (12 steps, tiny) ----------------
__global__ void __launch_bounds__(1024) scan_kernel()
{
    int bh = blockIdx.x, t = threadIdx.x;
    float acc = 0.f;
    for (int c=0;c<NCHUNK;c++){
        size_t o = ((size_t)bh*NCHUNK + c)*DH*DH + t;
        g_Spre[o] = acc; acc += g_Sloc[o];
    }
    if (t < DH){
        float a2 = 0.f;
        for (int c=0;c<NCHUNK;c++){
            size_t o = ((size_t)bh*NCHUNK + c)*DH + t;
            g_kpre[o] = a2; a2 += g_kloc[o];
        }
    }
}

// ---------------- attention output: intra-chunk masked + inter-chunk state ----------------
__global__ void __launch_bounds__(128) attn_kernel(const float* __restrict__ q,
                                                   const float* __restrict__ k,
                                                   const float* __restrict__ v,
                                                   float* __restrict__ a)
{
    int c = blockIdx.x, bh = blockIdx.y;
    int b = bh >> 3, h = bh & 7;
    __shared__ float ks[CHUNK][DH];
    __shared__ float vs[CHUNK][DH];
    __shared__ float Ss[DH][DH];
    __shared__ float kss[DH];
    int t = threadIdx.x;               // row within chunk, 0..127
    int base = b*NTOK + c*CHUNK;
    for (int idx=t; idx<CHUNK*DH; idx+=128){
        int row = idx >> 5, col = idx & 31;
        size_t g = (size_t)(base+row)*DM + h*DH + col;
        ks[row][col] = k[g];
        vs[row][col] = v[g];
    }
    for (int idx=t; idx<DH*DH; idx+=128)
        Ss[idx>>5][idx&31] = g_Spre[((size_t)bh*NCHUNK + c)*DH*DH + idx];
    if (t < DH) kss[t] = g_kpre[((size_t)bh*NCHUNK + c)*DH + t];
    __syncthreads();

    float qr[DH], num[DH];
    {
        const float4* qp = (const float4*)(q + (size_t)(base+t)*DM + h*DH);
        #pragma unroll
        for (int d4=0; d4<8; d4++){
            float4 w4 = qp[d4];
            qr[4*d4+0]=w4.x; qr[4*d4+1]=w4.y; qr[4*d4+2]=w4.z; qr[4*d4+3]=w4.w;
        }
    }
    #pragma unroll
    for (int m=0;m<DH;m++) num[m] = 0.f;
    float z = 0.f;

    // inter-chunk: num += q @ S_prev ; z += q . ksum_prev
    #pragma unroll
    for (int d=0; d<DH; d++){
        float qa = qr[d];
        z = fmaf(qa, kss[d], z);
        #pragma unroll
        for (int m=0;m<DH;m++) num[m] = fmaf(qa, Ss[d][m], num[m]);
    }
    // intra-chunk causal
    int jend = t | 31;                 // uniform per warp (rows are consecutive within warp)
    for (int j=0; j<=jend; j++){
        float aa = 0.f;
        #pragma unroll
        for (int d=0; d<DH; d++) aa = fmaf(qr[d], ks[j][d], aa);
        aa = (j <= t) ? aa : 0.f;
        z += aa;
        #pragma unroll
        for (int m=0;m<DH;m++) num[m] = fmaf(aa, vs[j][m], num[m]);
    }
    float inv = 1.f / (z + 1e-6f);
    float4* op = (float4*)(a + (size_t)(base+t)*DM + h*DH);
    #pragma unroll
    for (int d4=0; d4<8; d4++)
        op[d4] = make_float4(num[4*d4]*inv, num[4*d4+1]*inv, num[4*d4+2]*inv, num[4*d4+3]*inv);
}

// ---------------- LayerNorm (row of 256) ----------------
__global__ void __launch_bounds__(256) ln_kernel(const float* __restrict__ in,
                                                 const float* __restrict__ w,
                                                 const float* __restrict__ b,
                                                 float* __restrict__ out)
{
    __shared__ float red[8], red2[8];
    int r = blockIdx.x, t = threadIdx.x;
    float v = in[(size_t)r*DM + t];
    float s = v, s2 = v*v;
    #pragma unroll
    for (int o=16;o;o>>=1){ s += __shfl_xor_sync(~0u,s,o); s2 += __shfl_xor_sync(~0u,s2,o); }
    int warp = t >> 5, lane = t & 31;
    if (lane == 0){ red[warp] = s; red2[warp] = s2; }
    __syncthreads();
    float S=0.f, S2=0.f;
    #pragma unroll
    for (int i=0;i<8;i++){ S += red[i]; S2 += red2[i]; }
    float mean = S * (1.f/DM);
    float var  = S2 * (1.f/DM) - mean*mean;
    out[(size_t)r*DM + t] = (v - mean) * rsqrtf(var + 1e-5f) * w[t] + b[t];
}

// ---------------- head: mean / sigma ----------------
__global__ void __launch_bounds__(256) head_kernel(const float* __restrict__ x,
                                                   const float* __restrict__ mW, const float* __restrict__ mb,
                                                   const float* __restrict__ sW, const float* __restrict__ sb,
                                                   float* __restrict__ out)
{
    __shared__ float sx[DM];
    int r = blockIdx.x;                // 0..2047
    int b = r / SFUT, s = r % SFUT;
    const float* xr = x + (size_t)(b*NTOK + SPAST + s)*DM;
    int t = threadIdx.x;
    sx[t] = xr[t];
    __syncthreads();
    int warp = t >> 5, lane = t & 31;  // warp = output column (8 warps = 8 cols)
    float am = 0.f, as = 0.f;
    for (int kk=lane; kk<DM; kk+=32){
        float xv = sx[kk];
        am = fmaf(xv, mW[kk*8 + warp], am);
        as = fmaf(xv, sW[kk*8 + warp], as);
    }
    #pragma unroll
    for (int o=16;o;o>>=1){ am += __shfl_xor_sync(~0u,am,o); as += __shfl_xor_sync(~0u,as,o); }
    if (lane == 0){
        int o = r*8 + warp;
        out[o] = am + mb[warp];
        float sp = as + sb[warp];
        float spv = (sp > 20.f) ? sp : log1pf(expf(sp));
        out[BATCH*SFUT*8 + o] = 0.01f + 0.99f*spv;
    }
}

// ---------------- launch ----------------
extern "C" void kernel_launch(void* const* d_in, const int* in_sizes, int n_in,
                              void* d_out, int out_size)
{
    (void)in_sizes; (void)n_in; (void)out_size;
    const float* past_x   = (const float*)d_in[0];
    const float* past_y   = (const float*)d_in[1];
    const float* future_x = (const float*)d_in[2];
    const float* enc_W    = (const float*)d_in[3];
    const float* enc_b    = (const float*)d_in[4];
    const float* Wq  = (const float*)d_in[5];  const float* bq  = (const float*)d_in[6];
    const float* Wk  = (const float*)d_in[7];  const float* bk  = (const float*)d_in[8];
    const float* Wv  = (const float*)d_in[9];  const float* bv  = (const float*)d_in[10];
    const float* Wo  = (const float*)d_in[11]; const float* bo  = (const float*)d_in[12];
    const float* ln1w= (const float*)d_in[13]; const float* ln1b= (const float*)d_in[14];
    const float* W1  = (const float*)d_in[15]; const float* b1  = (const float*)d_in[16];
    const float* W2  = (const float*)d_in[17]; const float* b2  = (const float*)d_in[18];
    const float* ln2w= (const float*)d_in[19]; const float* ln2b= (const float*)d_in[20];
    const float* mW  = (const float*)d_in[21]; const float* mb  = (const float*)d_in[22];
    const float* sW  = (const float*)d_in[23]; const float* sb  = (const float*)d_in[24];

    float *x,*tmp,*q,*k,*v,*a,*h;
    cudaGetSymbolAddress((void**)&x,   g_x);
    cudaGetSymbolAddress((void**)&tmp, g_tmp);
    cudaGetSymbolAddress((void**)&q,   g_qb);
    cudaGetSymbolAddress((void**)&k,   g_kb);
    cudaGetSymbolAddress((void**)&v,   g_vb);
    cudaGetSymbolAddress((void**)&a,   g_ab);
    cudaGetSymbolAddress((void**)&h,   g_hb);

    embed_kernel<<<NROWS, 256>>>(past_x, past_y, future_x, enc_W, enc_b, x);

    dim3 gD (DM/GBN,  NROWS/GBM);   // 4 x 48
    dim3 gFF(DFF/GBN, NROWS/GBM);   // 32 x 48
    dim3 gA (NCHUNK, NBH);          // 12 x 32

    for (int i=0;i<NLAYERS;i++){
        const float* wq = Wq + (size_t)i*DM*DM;  const float* vbq = bq + i*DM;
        const float* wk = Wk + (size_t)i*DM*DM;  const float* vbk = bk + i*DM;
        const float* wv = Wv + (size_t)i*DM*DM;  const float* vbv = bv + i*DM;
        const float* wo = Wo + (size_t)i*DM*DM;  const float* vbo = bo + i*DM;
        const float* w1 = W1 + (size_t)i*DM*DFF; const float* vb1 = b1 + i*DFF;
        const float* w2 = W2 + (size_t)i*DFF*DM; const float* vb2 = b2 + i*DM;

        sgemm_kernel<1><<<gD, 256>>>(DM, DM, x, wq, vbq, nullptr, q);   // q = elu+1
        sgemm_kernel<1><<<gD, 256>>>(DM, DM, x, wk, vbk, nullptr, k);   // k = elu+1
        sgemm_kernel<0><<<gD, 256>>>(DM, DM, x, wv, vbv, nullptr, v);

        chunk_kv_kernel<<<gA, 1024>>>(k, v);
        scan_kernel<<<NBH, 1024>>>();
        attn_kernel<<<gA, 128>>>(q, k, v, a);

        sgemm_kernel<3><<<gD, 256>>>(DM, DM, a, wo, vbo, x, tmp);       // tmp = x + a@Wo + bo
        ln_kernel<<<NROWS, 256>>>(tmp, ln1w + i*DM, ln1b + i*DM, x);

        sgemm_kernel<2><<<gFF, 256>>>(DM, DFF, x, w1, vb1, nullptr, h); // h = relu
        sgemm_kernel<3><<<gD, 256>>>(DFF, DM, h, w2, vb2, x, tmp);      // tmp = x + h@W2 + b2
        ln_kernel<<<NROWS, 256>>>(tmp, ln2w + i*DM, ln2b + i*DM, x);
    }

    head_kernel<<<BATCH*SFUT, 256>>>(x, mW, mb, sW, sb, (float*)d_out);
}